// round 1
// baseline (speedup 1.0000x reference)
#include <cuda_runtime.h>

#define CDIM   256
#define NNODES 65536
#define NEDGES 131072

// -------- scratch (device globals; no runtime allocation allowed) --------
__device__ float g_xp_a[NNODES * CDIM];
__device__ float g_xp_b[NNODES * CDIM];
__device__ float g_out_a[NNODES * CDIM];
__device__ float g_out_b[NNODES * CDIM];

// ======================================================================
// GEMM: C[m][n] = sum_k A[m][k] * W[n][k] + bias[n]
// A: M x 256 row-major, W: 256 x 256 row-major (so this is A @ W^T).
// BM=32, BN=256, BK=32, 256 threads, 4x8 micro-tile per thread.
// ======================================================================
__global__ __launch_bounds__(256) void gemm_bias_kernel(
    const float* __restrict__ A, const float* __restrict__ W,
    const float* __restrict__ bias, float* __restrict__ Cmat)
{
    __shared__ float As[32][33];
    __shared__ float Bs[256][33];
    const int tid = threadIdx.x;
    const int tx = tid & 31;   // column lane
    const int ty = tid >> 5;   // warp id -> rows ty*4 .. ty*4+3
    const int m0 = blockIdx.x * 32;

    float acc[4][8];
#pragma unroll
    for (int i = 0; i < 4; i++)
#pragma unroll
        for (int j = 0; j < 8; j++) acc[i][j] = 0.f;

    const int lr = tid >> 3;        // 0..31
    const int lc = (tid & 7) * 4;   // 0,4,..28

    for (int k0 = 0; k0 < CDIM; k0 += 32) {
        float4 va = *reinterpret_cast<const float4*>(A + (size_t)(m0 + lr) * CDIM + k0 + lc);
        As[lr][lc] = va.x; As[lr][lc + 1] = va.y; As[lr][lc + 2] = va.z; As[lr][lc + 3] = va.w;
#pragma unroll
        for (int pass = 0; pass < 8; pass++) {
            int n = lr + pass * 32;
            float4 vb = *reinterpret_cast<const float4*>(W + (size_t)n * CDIM + k0 + lc);
            Bs[n][lc] = vb.x; Bs[n][lc + 1] = vb.y; Bs[n][lc + 2] = vb.z; Bs[n][lc + 3] = vb.w;
        }
        __syncthreads();
#pragma unroll
        for (int k = 0; k < 32; k++) {
            float a[4], b[8];
#pragma unroll
            for (int i = 0; i < 4; i++) a[i] = As[ty * 4 + i][k];
#pragma unroll
            for (int j = 0; j < 8; j++) b[j] = Bs[j * 32 + tx][k];
#pragma unroll
            for (int i = 0; i < 4; i++)
#pragma unroll
                for (int j = 0; j < 8; j++) acc[i][j] = fmaf(a[i], b[j], acc[i][j]);
        }
        __syncthreads();
    }
#pragma unroll
    for (int i = 0; i < 4; i++)
#pragma unroll
        for (int j = 0; j < 8; j++) {
            int col = j * 32 + tx;
            Cmat[(size_t)(m0 + ty * 4 + i) * CDIM + col] = acc[i][j] + __ldg(bias + col);
        }
}

// Same GEMM, epilogue = bias + LayerNorm over the full row (warp owns 4 rows).
__global__ __launch_bounds__(256) void gemm_ln_kernel(
    const float* __restrict__ A, const float* __restrict__ W,
    const float* __restrict__ bias, const float* __restrict__ lng,
    const float* __restrict__ lnb, float* __restrict__ Y)
{
    __shared__ float As[32][33];
    __shared__ float Bs[256][33];
    const int tid = threadIdx.x;
    const int tx = tid & 31;
    const int ty = tid >> 5;
    const int m0 = blockIdx.x * 32;

    float acc[4][8];
#pragma unroll
    for (int i = 0; i < 4; i++)
#pragma unroll
        for (int j = 0; j < 8; j++) acc[i][j] = 0.f;

    const int lr = tid >> 3;
    const int lc = (tid & 7) * 4;

    for (int k0 = 0; k0 < CDIM; k0 += 32) {
        float4 va = *reinterpret_cast<const float4*>(A + (size_t)(m0 + lr) * CDIM + k0 + lc);
        As[lr][lc] = va.x; As[lr][lc + 1] = va.y; As[lr][lc + 2] = va.z; As[lr][lc + 3] = va.w;
#pragma unroll
        for (int pass = 0; pass < 8; pass++) {
            int n = lr + pass * 32;
            float4 vb = *reinterpret_cast<const float4*>(W + (size_t)n * CDIM + k0 + lc);
            Bs[n][lc] = vb.x; Bs[n][lc + 1] = vb.y; Bs[n][lc + 2] = vb.z; Bs[n][lc + 3] = vb.w;
        }
        __syncthreads();
#pragma unroll
        for (int k = 0; k < 32; k++) {
            float a[4], b[8];
#pragma unroll
            for (int i = 0; i < 4; i++) a[i] = As[ty * 4 + i][k];
#pragma unroll
            for (int j = 0; j < 8; j++) b[j] = Bs[j * 32 + tx][k];
#pragma unroll
            for (int i = 0; i < 4; i++)
#pragma unroll
                for (int j = 0; j < 8; j++) acc[i][j] = fmaf(a[i], b[j], acc[i][j]);
        }
        __syncthreads();
    }

#pragma unroll
    for (int i = 0; i < 4; i++) {
        float v[8];
        float s = 0.f, sq = 0.f;
#pragma unroll
        for (int j = 0; j < 8; j++) {
            v[j] = acc[i][j] + __ldg(bias + j * 32 + tx);
            s += v[j];
        }
#pragma unroll
        for (int j = 0; j < 8; j++) sq = fmaf(v[j], v[j], sq);
#pragma unroll
        for (int off = 16; off > 0; off >>= 1) {
            s  += __shfl_xor_sync(0xffffffffu, s, off);
            sq += __shfl_xor_sync(0xffffffffu, sq, off);
        }
        float mean = s * (1.f / 256.f);
        float var  = sq * (1.f / 256.f) - mean * mean;
        float rs   = rsqrtf(var + 1e-5f);
#pragma unroll
        for (int j = 0; j < 8; j++) {
            int col = j * 32 + tx;
            Y[(size_t)(m0 + ty * 4 + i) * CDIM + col] =
                (v[j] - mean) * rs * __ldg(lng + col) + __ldg(lnb + col);
        }
    }
}

// ======================================================================
// zero accumulators
// ======================================================================
__global__ void zero_kernel(float4* __restrict__ a, float4* __restrict__ b, int n4)
{
    int i = blockIdx.x * blockDim.x + threadIdx.x;
    const float4 z = make_float4(0.f, 0.f, 0.f, 0.f);
    for (; i < n4; i += gridDim.x * blockDim.x) { a[i] = z; b[i] = z; }
}

// ======================================================================
// Edge-message kernel: per 32-edge tile
//   gather dst/src rows -> Q,K projections (fused GEMM) -> 4x4 attention per
//   head -> combine with v = ea*P1 + P2 (V GEMM eliminated algebraically)
//   -> Wout projection -> atomicAdd scatter into out accumulator.
// ======================================================================
struct EdgeSmem {
    float Wqk[128][65];   // rows 0..63 = Wq[j][k], 64..127 = Wk[j][k]
    float Wo[64][65];     // Wout[j][k]
    float P1[4][64];      // We-chunk . Wv-row
    float P2[4][64];      // be-chunk . Wv-row + bv
    float bq[64], bk[64], bo[64];
    float eas[32];
    int   sidx[32], didx[32];
    float bufD[32][260];  // dst rows, later reused for o
    float bufS[32][260];  // src rows
    float bufQ[32][260];
    float bufK[32][260];
    float aB[32][68];     // softmax coefficients a[e][(h*4+p)*4+pk]
};

__global__ __launch_bounds__(256, 1) void edge_kernel(
    const float* __restrict__ xp_s, const float* __restrict__ xp_d,
    const int* __restrict__ ei, const float* __restrict__ ea,
    const float* __restrict__ We, const float* __restrict__ be,
    const float* __restrict__ Win, const float* __restrict__ bin,
    const float* __restrict__ Wout, const float* __restrict__ bout,
    float* __restrict__ outAcc)
{
    extern __shared__ char smemRaw[];
    EdgeSmem& S = *reinterpret_cast<EdgeSmem*>(smemRaw);
    const int tid = threadIdx.x;

    // ---- per-block setup: weights + P1/P2 + biases ----
    for (int i = tid; i < 128 * 64; i += 256) S.Wqk[i >> 6][i & 63] = Win[i];
    for (int i = tid; i < 64 * 64; i += 256) S.Wo[i >> 6][i & 63] = Wout[i];
    if (tid < 64) { S.bq[tid] = bin[tid]; S.bk[tid] = bin[64 + tid]; S.bo[tid] = bout[tid]; }
    {
        int p = tid >> 6, j = tid & 63;               // 256 threads -> all (p,j)
        const float* wv = Win + (size_t)(128 + j) * 64;
        float s1 = 0.f, s2 = 0.f;
#pragma unroll 8
        for (int k = 0; k < 64; k++) {
            float w = wv[k];
            s1 = fmaf(__ldg(We + p * 64 + k), w, s1);
            s2 = fmaf(__ldg(be + p * 64 + k), w, s2);
        }
        S.P1[p][j] = s1;
        S.P2[p][j] = s2 + __ldg(bin + 128 + j);
    }
    const int e0 = blockIdx.x * 32;
    if (tid < 32) {
        S.eas[tid]  = ea[e0 + tid];
        S.sidx[tid] = ei[e0 + tid];            // ei[0][e]
        S.didx[tid] = ei[NEDGES + e0 + tid];   // ei[1][e]
    }
    __syncthreads();

    // ---- gather dst / src rows ----
    {
        int e  = tid >> 3;
        int c0 = (tid & 7) * 4;
        const float* dRow = xp_d + (size_t)S.didx[e] * CDIM;
        const float* sRow = xp_s + (size_t)S.sidx[e] * CDIM;
#pragma unroll
        for (int pass = 0; pass < 8; pass++) {
            int c = pass * 32 + c0;
            *reinterpret_cast<float4*>(&S.bufD[e][c]) = *reinterpret_cast<const float4*>(dRow + c);
            *reinterpret_cast<float4*>(&S.bufS[e][c]) = *reinterpret_cast<const float4*>(sRow + c);
        }
    }
    __syncthreads();

    const int g  = tid >> 4;   // 0..15 -> rows g*8..g*8+7 of the 128-row (e,p) space
    const int tx = tid & 15;   // 0..15 -> cols tx+16j

    int eIdx[8], pOff[8];
#pragma unroll
    for (int i = 0; i < 8; i++) { int r = g * 8 + i; eIdx[i] = r >> 2; pOff[i] = (r & 3) * 64; }

    // ---- fused Q & K projection: 128x64x64 GEMMs ----
    {
        float accQ[8][4], accK[8][4];
#pragma unroll
        for (int i = 0; i < 8; i++)
#pragma unroll
            for (int j = 0; j < 4; j++) { accQ[i][j] = 0.f; accK[i][j] = 0.f; }
#pragma unroll 4
        for (int k = 0; k < 64; k++) {
            float aD[8], aS[8], bQ[4], bK[4];
#pragma unroll
            for (int i = 0; i < 8; i++) {
                aD[i] = S.bufD[eIdx[i]][pOff[i] + k];
                aS[i] = S.bufS[eIdx[i]][pOff[i] + k];
            }
#pragma unroll
            for (int j = 0; j < 4; j++) {
                int col = j * 16 + tx;
                bQ[j] = S.Wqk[col][k];
                bK[j] = S.Wqk[64 + col][k];
            }
#pragma unroll
            for (int i = 0; i < 8; i++)
#pragma unroll
                for (int j = 0; j < 4; j++) {
                    accQ[i][j] = fmaf(aD[i], bQ[j], accQ[i][j]);
                    accK[i][j] = fmaf(aS[i], bK[j], accK[i][j]);
                }
        }
#pragma unroll
        for (int i = 0; i < 8; i++)
#pragma unroll
            for (int j = 0; j < 4; j++) {
                int col = j * 16 + tx;
                S.bufQ[eIdx[i]][pOff[i] + col] = accQ[i][j] + S.bq[col];
                S.bufK[eIdx[i]][pOff[i] + col] = accK[i][j] + S.bk[col];
            }
    }
    __syncthreads();

    // ---- attention: 32 edges x (h,p) = 512 tasks, softmax over 4 keys ----
#pragma unroll
    for (int t = tid; t < 512; t += 256) {
        int e = t >> 4, h = (t >> 2) & 3, p = t & 3;
        const float* qp = &S.bufQ[e][p * 64 + h * 16];
        float4 q0 = *reinterpret_cast<const float4*>(qp + 0);
        float4 q1 = *reinterpret_cast<const float4*>(qp + 4);
        float4 q2 = *reinterpret_cast<const float4*>(qp + 8);
        float4 q3 = *reinterpret_cast<const float4*>(qp + 12);
        float sc[4];
#pragma unroll
        for (int pk = 0; pk < 4; pk++) {
            const float* kp = &S.bufK[e][pk * 64 + h * 16];
            float4 k0 = *reinterpret_cast<const float4*>(kp + 0);
            float4 k1 = *reinterpret_cast<const float4*>(kp + 4);
            float4 k2 = *reinterpret_cast<const float4*>(kp + 8);
            float4 k3 = *reinterpret_cast<const float4*>(kp + 12);
            float d = q0.x * k0.x + q0.y * k0.y + q0.z * k0.z + q0.w * k0.w
                    + q1.x * k1.x + q1.y * k1.y + q1.z * k1.z + q1.w * k1.w
                    + q2.x * k2.x + q2.y * k2.y + q2.z * k2.z + q2.w * k2.w
                    + q3.x * k3.x + q3.y * k3.y + q3.z * k3.z + q3.w * k3.w;
            sc[pk] = d * 0.25f;   // SCALE = HD^-0.5 = 0.25
        }
        float mx = fmaxf(fmaxf(sc[0], sc[1]), fmaxf(sc[2], sc[3]));
        float ex[4], ssum = 0.f;
#pragma unroll
        for (int pk = 0; pk < 4; pk++) { ex[pk] = __expf(sc[pk] - mx); ssum += ex[pk]; }
        float inv = 1.f / ssum;
#pragma unroll
        for (int pk = 0; pk < 4; pk++) S.aB[e][((h * 4 + p) << 2) + pk] = ex[pk] * inv;
    }
    __syncthreads();

    // ---- combine: o = sum_pk a * (ea*P1 + P2) -> reuse bufD ----
    {
        float o[8][4];
#pragma unroll
        for (int j = 0; j < 4; j++) {
            int col = j * 16 + tx;   // h = j, d = tx
            float p1v[4], p2v[4];
#pragma unroll
            for (int pk = 0; pk < 4; pk++) { p1v[pk] = S.P1[pk][col]; p2v[pk] = S.P2[pk][col]; }
#pragma unroll
            for (int i = 0; i < 8; i++) {
                int e = eIdx[i], p = pOff[i] >> 6;
                float eaV = S.eas[e];
                float acc = 0.f;
#pragma unroll
                for (int pk = 0; pk < 4; pk++) {
                    float a = S.aB[e][((j * 4 + p) << 2) + pk];
                    acc = fmaf(a, fmaf(eaV, p1v[pk], p2v[pk]), acc);
                }
                o[i][j] = acc;
            }
        }
#pragma unroll
        for (int i = 0; i < 8; i++)
#pragma unroll
            for (int j = 0; j < 4; j++)
                S.bufD[eIdx[i]][pOff[i] + j * 16 + tx] = o[i][j];
    }
    __syncthreads();

    // ---- output projection (128x64x64) + scatter-add ----
    {
        float acc[8][4];
#pragma unroll
        for (int i = 0; i < 8; i++)
#pragma unroll
            for (int j = 0; j < 4; j++) acc[i][j] = 0.f;
#pragma unroll 4
        for (int k = 0; k < 64; k++) {
            float a[8], b[4];
#pragma unroll
            for (int i = 0; i < 8; i++) a[i] = S.bufD[eIdx[i]][pOff[i] + k];
#pragma unroll
            for (int j = 0; j < 4; j++) b[j] = S.Wo[j * 16 + tx][k];
#pragma unroll
            for (int i = 0; i < 8; i++)
#pragma unroll
                for (int j = 0; j < 4; j++) acc[i][j] = fmaf(a[i], b[j], acc[i][j]);
        }
#pragma unroll
        for (int i = 0; i < 8; i++) {
            float* dstRow = outAcc + (size_t)S.didx[eIdx[i]] * CDIM + pOff[i];
#pragma unroll
            for (int j = 0; j < 4; j++) {
                int col = j * 16 + tx;
                atomicAdd(dstRow + col, acc[i][j] + S.bo[col]);
            }
        }
    }
}

// ======================================================================
// launch
// ======================================================================
extern "C" void kernel_launch(void* const* d_in, const int* in_sizes, int n_in,
                              void* d_out, int out_size)
{
    const float* x_a   = (const float*)d_in[0];
    const float* x_b   = (const float*)d_in[1];
    const int*   ei1   = (const int*)  d_in[2];
    const float* ea1   = (const float*)d_in[3];
    const int*   ei2   = (const int*)  d_in[4];
    const float* ea2   = (const float*)d_in[5];
    const float* Wn_a  = (const float*)d_in[6];
    const float* bn_a  = (const float*)d_in[7];
    const float* Wn_b  = (const float*)d_in[8];
    const float* bn_b  = (const float*)d_in[9];
    const float* We1   = (const float*)d_in[10];
    const float* be1   = (const float*)d_in[11];
    const float* Win1  = (const float*)d_in[12];
    const float* bin1  = (const float*)d_in[13];
    const float* Wout1 = (const float*)d_in[14];
    const float* bout1 = (const float*)d_in[15];
    const float* We2   = (const float*)d_in[16];
    const float* be2   = (const float*)d_in[17];
    const float* Win2  = (const float*)d_in[18];
    const float* bin2  = (const float*)d_in[19];
    const float* Wout2 = (const float*)d_in[20];
    const float* bout2 = (const float*)d_in[21];
    const float* Wo_a  = (const float*)d_in[22];
    const float* bo_a  = (const float*)d_in[23];
    const float* Wo_b  = (const float*)d_in[24];
    const float* bo_b  = (const float*)d_in[25];
    const float* ln_g  = (const float*)d_in[26];
    const float* ln_b  = (const float*)d_in[27];
    float* y = (float*)d_out;

    float *xpa, *xpb, *oa, *ob;
    cudaGetSymbolAddress((void**)&xpa, g_xp_a);
    cudaGetSymbolAddress((void**)&xpb, g_xp_b);
    cudaGetSymbolAddress((void**)&oa,  g_out_a);
    cudaGetSymbolAddress((void**)&ob,  g_out_b);

    cudaFuncSetAttribute(edge_kernel, cudaFuncAttributeMaxDynamicSharedMemorySize,
                         (int)sizeof(EdgeSmem));

    // node projections
    gemm_bias_kernel<<<NNODES / 32, 256>>>(x_a, Wn_a, bn_a, xpa);
    gemm_bias_kernel<<<NNODES / 32, 256>>>(x_b, Wn_b, bn_b, xpb);

    // zero accumulators
    zero_kernel<<<2048, 256>>>((float4*)oa, (float4*)ob, NNODES * CDIM / 4);

    // edge messages (set 1: src=xp_a, dst=xp_b -> out_b ; set 2 mirrored)
    edge_kernel<<<NEDGES / 32, 256, sizeof(EdgeSmem)>>>(
        xpa, xpb, ei1, ea1, We1, be1, Win1, bin1, Wout1, bout1, ob);
    edge_kernel<<<NEDGES / 32, 256, sizeof(EdgeSmem)>>>(
        xpb, xpa, ei2, ea2, We2, be2, Win2, bin2, Wout2, bout2, oa);

    // output projection + layernorm
    gemm_ln_kernel<<<NNODES / 32, 256>>>(oa, Wo_a, bo_a, ln_g, ln_b, y);
    gemm_ln_kernel<<<NNODES / 32, 256>>>(ob, Wo_b, bo_b, ln_g, ln_b,
                                         y + (size_t)NNODES * CDIM);
}

// round 5
// speedup vs baseline: 1.6569x; 1.6569x over previous
#include <cuda_runtime.h>

#define CDIM   256
#define NNODES 65536
#define NEDGES 131072

// -------- scratch (device globals; no runtime allocation allowed) --------
__device__ float g_xp_a[NNODES * CDIM];
__device__ float g_xp_b[NNODES * CDIM];
__device__ float g_out_a[NNODES * CDIM];
__device__ float g_out_b[NNODES * CDIM];
// Q/K tables: node-major, 256 floats per node (4 chunks x 64)
__device__ float g_Q1[NNODES * CDIM];   // Q for set1 (from xp_b, Wq1)
__device__ float g_K1[NNODES * CDIM];   // K for set1 (from xp_a, Wk1)
__device__ float g_Q2[NNODES * CDIM];   // Q for set2 (from xp_a, Wq2)
__device__ float g_K2[NNODES * CDIM];   // K for set2 (from xp_b, Wk2)
// Folded V*Wout tables per set: index (h*4+kp)*64 + c
__device__ float g_U1[2][1024];
__device__ float g_U2[2][1024];

// ======================================================================
// GEMM: C[m][n] = sum_k A[m][k] * W[n][k] + bias[n]
// A: M x 256 row-major, W: 256 x 256 row-major (A @ W^T).
// BM=32, BN=256, BK=32, 256 threads, 4x8 micro-tile per thread.
// ======================================================================
__global__ __launch_bounds__(256) void gemm_bias_kernel(
    const float* __restrict__ A, const float* __restrict__ W,
    const float* __restrict__ bias, float* __restrict__ Cmat)
{
    __shared__ float As[32][33];
    __shared__ float Bs[256][33];
    const int tid = threadIdx.x;
    const int tx = tid & 31;
    const int ty = tid >> 5;
    const int m0 = blockIdx.x * 32;

    float acc[4][8];
#pragma unroll
    for (int i = 0; i < 4; i++)
#pragma unroll
        for (int j = 0; j < 8; j++) acc[i][j] = 0.f;

    const int lr = tid >> 3;
    const int lc = (tid & 7) * 4;

    for (int k0 = 0; k0 < CDIM; k0 += 32) {
        float4 va = *reinterpret_cast<const float4*>(A + (size_t)(m0 + lr) * CDIM + k0 + lc);
        As[lr][lc] = va.x; As[lr][lc + 1] = va.y; As[lr][lc + 2] = va.z; As[lr][lc + 3] = va.w;
#pragma unroll
        for (int pass = 0; pass < 8; pass++) {
            int n = lr + pass * 32;
            float4 vb = *reinterpret_cast<const float4*>(W + (size_t)n * CDIM + k0 + lc);
            Bs[n][lc] = vb.x; Bs[n][lc + 1] = vb.y; Bs[n][lc + 2] = vb.z; Bs[n][lc + 3] = vb.w;
        }
        __syncthreads();
#pragma unroll
        for (int k = 0; k < 32; k++) {
            float a[4], b[8];
#pragma unroll
            for (int i = 0; i < 4; i++) a[i] = As[ty * 4 + i][k];
#pragma unroll
            for (int j = 0; j < 8; j++) b[j] = Bs[j * 32 + tx][k];
#pragma unroll
            for (int i = 0; i < 4; i++)
#pragma unroll
                for (int j = 0; j < 8; j++) acc[i][j] = fmaf(a[i], b[j], acc[i][j]);
        }
        __syncthreads();
    }
#pragma unroll
    for (int i = 0; i < 4; i++)
#pragma unroll
        for (int j = 0; j < 8; j++) {
            int col = j * 32 + tx;
            Cmat[(size_t)(m0 + ty * 4 + i) * CDIM + col] = acc[i][j] + __ldg(bias + col);
        }
}

// Same GEMM, epilogue = bias + LayerNorm over the full row (warp owns 4 rows).
__global__ __launch_bounds__(256) void gemm_ln_kernel(
    const float* __restrict__ A, const float* __restrict__ W,
    const float* __restrict__ bias, const float* __restrict__ lng,
    const float* __restrict__ lnb, float* __restrict__ Y)
{
    __shared__ float As[32][33];
    __shared__ float Bs[256][33];
    const int tid = threadIdx.x;
    const int tx = tid & 31;
    const int ty = tid >> 5;
    const int m0 = blockIdx.x * 32;

    float acc[4][8];
#pragma unroll
    for (int i = 0; i < 4; i++)
#pragma unroll
        for (int j = 0; j < 8; j++) acc[i][j] = 0.f;

    const int lr = tid >> 3;
    const int lc = (tid & 7) * 4;

    for (int k0 = 0; k0 < CDIM; k0 += 32) {
        float4 va = *reinterpret_cast<const float4*>(A + (size_t)(m0 + lr) * CDIM + k0 + lc);
        As[lr][lc] = va.x; As[lr][lc + 1] = va.y; As[lr][lc + 2] = va.z; As[lr][lc + 3] = va.w;
#pragma unroll
        for (int pass = 0; pass < 8; pass++) {
            int n = lr + pass * 32;
            float4 vb = *reinterpret_cast<const float4*>(W + (size_t)n * CDIM + k0 + lc);
            Bs[n][lc] = vb.x; Bs[n][lc + 1] = vb.y; Bs[n][lc + 2] = vb.z; Bs[n][lc + 3] = vb.w;
        }
        __syncthreads();
#pragma unroll
        for (int k = 0; k < 32; k++) {
            float a[4], b[8];
#pragma unroll
            for (int i = 0; i < 4; i++) a[i] = As[ty * 4 + i][k];
#pragma unroll
            for (int j = 0; j < 8; j++) b[j] = Bs[j * 32 + tx][k];
#pragma unroll
            for (int i = 0; i < 4; i++)
#pragma unroll
                for (int j = 0; j < 8; j++) acc[i][j] = fmaf(a[i], b[j], acc[i][j]);
        }
        __syncthreads();
    }

#pragma unroll
    for (int i = 0; i < 4; i++) {
        float v[8];
        float s = 0.f, sq = 0.f;
#pragma unroll
        for (int j = 0; j < 8; j++) {
            v[j] = acc[i][j] + __ldg(bias + j * 32 + tx);
            s += v[j];
        }
#pragma unroll
        for (int j = 0; j < 8; j++) sq = fmaf(v[j], v[j], sq);
#pragma unroll
        for (int off = 16; off > 0; off >>= 1) {
            s  += __shfl_xor_sync(0xffffffffu, s, off);
            sq += __shfl_xor_sync(0xffffffffu, sq, off);
        }
        float mean = s * (1.f / 256.f);
        float var  = sq * (1.f / 256.f) - mean * mean;
        float rs   = rsqrtf(var + 1e-5f);
#pragma unroll
        for (int j = 0; j < 8; j++) {
            int col = j * 32 + tx;
            Y[(size_t)(m0 + ty * 4 + i) * CDIM + col] =
                (v[j] - mean) * rs * __ldg(lng + col) + __ldg(lnb + col);
        }
    }
}

// ======================================================================
// Q/K table kernel: xp viewed as (4N, 64) row-major; two 64x64 projections
// (same weights for all 4 chunks of a node -> flat GEMM on the chunk view).
// T1[r][c] = sum_k xp[r][k]*W1[c][k] + b1[c];  T2 likewise.
// Block: 64 rows x 64 cols, 256 threads, 4x4 micro-tile x 2 outputs.
// Dynamic smem (49.7 KB > 48 KB static limit).
// ======================================================================
struct QKSmem {
    float X[64][64];     // broadcast read pattern -> no padding needed
    float W1s[64][65];
    float W2s[64][65];
};

__global__ __launch_bounds__(256) void qk_kernel(
    const float* __restrict__ xp,
    const float* __restrict__ W1, const float* __restrict__ b1,
    const float* __restrict__ W2, const float* __restrict__ b2,
    float* __restrict__ T1, float* __restrict__ T2)
{
    extern __shared__ char qkRaw[];
    QKSmem& S = *reinterpret_cast<QKSmem*>(qkRaw);
    const int tid = threadIdx.x;
    const int r0 = blockIdx.x * 64;

    for (int i = tid; i < 4096; i += 256) {
        S.W1s[i >> 6][i & 63] = W1[i];
        S.W2s[i >> 6][i & 63] = W2[i];
    }
    // load X tile: 64 rows x 64 cols = 1024 float4
    for (int p = 0; p < 4; p++) {
        int idx = tid + p * 256;
        int row = idx >> 4, c4 = (idx & 15) * 4;
        float4 v = *reinterpret_cast<const float4*>(xp + (size_t)(r0 + row) * 64 + c4);
        *reinterpret_cast<float4*>(&S.X[row][c4]) = v;
    }
    __syncthreads();

    const int ty = tid >> 4;   // rows ty*4 + i
    const int tx = tid & 15;   // cols j*16 + tx

    float acc1[4][4], acc2[4][4];
#pragma unroll
    for (int i = 0; i < 4; i++)
#pragma unroll
        for (int j = 0; j < 4; j++) { acc1[i][j] = 0.f; acc2[i][j] = 0.f; }

#pragma unroll 4
    for (int k = 0; k < 64; k++) {
        float a[4], w1[4], w2[4];
#pragma unroll
        for (int i = 0; i < 4; i++) a[i] = S.X[ty * 4 + i][k];
#pragma unroll
        for (int j = 0; j < 4; j++) {
            int col = j * 16 + tx;
            w1[j] = S.W1s[col][k];
            w2[j] = S.W2s[col][k];
        }
#pragma unroll
        for (int i = 0; i < 4; i++)
#pragma unroll
            for (int j = 0; j < 4; j++) {
                acc1[i][j] = fmaf(a[i], w1[j], acc1[i][j]);
                acc2[i][j] = fmaf(a[i], w2[j], acc2[i][j]);
            }
    }
#pragma unroll
    for (int i = 0; i < 4; i++)
#pragma unroll
        for (int j = 0; j < 4; j++) {
            int col = j * 16 + tx;
            size_t off = (size_t)(r0 + ty * 4 + i) * 64 + col;
            T1[off] = acc1[i][j] + __ldg(b1 + col);
            T2[off] = acc2[i][j] + __ldg(b2 + col);
        }
}

// ======================================================================
// setup kernel: fold V and Wout into tiny U1/U2 tables.
//   P1[kp][j] = sum_t We[kp*64+t]*Wv[j][t]
//   P2[kp][j] = sum_t be[kp*64+t]*Wv[j][t] + bv[j]
//   U1[(h*4+kp)*64+c] = sum_{d<16} P1[kp][h*16+d]*Wout[c][h*16+d]   (U2 same)
// ======================================================================
__global__ __launch_bounds__(256) void setup_kernel(
    const float* __restrict__ We, const float* __restrict__ be,
    const float* __restrict__ Win, const float* __restrict__ bin,
    const float* __restrict__ Wout,
    float* __restrict__ U1, float* __restrict__ U2)
{
    __shared__ float P1[4][64], P2[4][64];
    const int tid = threadIdx.x;
    {
        int kp = tid >> 6, j = tid & 63;
        const float* wv = Win + (size_t)(128 + j) * 64;
        float s1 = 0.f, s2 = 0.f;
#pragma unroll 8
        for (int t = 0; t < 64; t++) {
            float w = wv[t];
            s1 = fmaf(__ldg(We + kp * 64 + t), w, s1);
            s2 = fmaf(__ldg(be + kp * 64 + t), w, s2);
        }
        P1[kp][j] = s1;
        P2[kp][j] = s2 + __ldg(bin + 128 + j);
    }
    __syncthreads();
    for (int idx = tid; idx < 1024; idx += 256) {
        int h = idx >> 8, kp = (idx >> 6) & 3, c = idx & 63;
        float u1 = 0.f, u2 = 0.f;
#pragma unroll
        for (int d = 0; d < 16; d++) {
            float wo = __ldg(Wout + (size_t)c * 64 + h * 16 + d);
            u1 = fmaf(P1[kp][h * 16 + d], wo, u1);
            u2 = fmaf(P2[kp][h * 16 + d], wo, u2);
        }
        U1[(h * 4 + kp) * 64 + c] = u1;
        U2[(h * 4 + kp) * 64 + c] = u2;
    }
}

// ======================================================================
// zero accumulators
// ======================================================================
__global__ void zero_kernel(float4* __restrict__ a, float4* __restrict__ b, int n4)
{
    int i = blockIdx.x * blockDim.x + threadIdx.x;
    const float4 z = make_float4(0.f, 0.f, 0.f, 0.f);
    for (; i < n4; i += gridDim.x * blockDim.x) { a[i] = z; b[i] = z; }
}

// ======================================================================
// Lightweight edge kernel: 1 warp per edge, 8 edges per block.
//   gather q(dst),k(src) rows -> 64 scores (16-dim dots) -> quad softmax ->
//   m[q,c] = sum_{h,kp} a * (ea*U1 + U2) + bout -> red.v2 scatter.
// ======================================================================
#define EPB 8
__global__ __launch_bounds__(256) void edge_kernel2(
    const float* __restrict__ Qt, const float* __restrict__ Kt,
    const int* __restrict__ ei, const float* __restrict__ ea,
    const float* __restrict__ U1, const float* __restrict__ U2,
    const float* __restrict__ bout, float* __restrict__ outAcc)
{
    __shared__ float u1S[16][64];
    __shared__ float u2S[16][64];
    __shared__ float qS[EPB][256];
    __shared__ float kS[EPB][256];
    __shared__ float aS[EPB][64];
    __shared__ float boS[64];

    const int tid = threadIdx.x;
    const int w = tid >> 5;
    const int l = tid & 31;

    for (int i = tid; i < 1024; i += 256) {
        u1S[i >> 6][i & 63] = U1[i];
        u2S[i >> 6][i & 63] = U2[i];
    }
    if (tid < 64) boS[tid] = bout[tid];

    const int e = blockIdx.x * EPB + w;
    const int s_node = ei[e];
    const int d_node = ei[NEDGES + e];
    const float eav = ea[e];

    // gather q (dst) and k (src) rows: 256 floats each, coalesced
    {
        const float4* qrow = reinterpret_cast<const float4*>(Qt + (size_t)d_node * 256);
        const float4* krow = reinterpret_cast<const float4*>(Kt + (size_t)s_node * 256);
        float4 qa = qrow[l], qb = qrow[l + 32];
        float4 ka = krow[l], kb = krow[l + 32];
        reinterpret_cast<float4*>(qS[w])[l] = qa;
        reinterpret_cast<float4*>(qS[w])[l + 32] = qb;
        reinterpret_cast<float4*>(kS[w])[l] = ka;
        reinterpret_cast<float4*>(kS[w])[l + 32] = kb;
    }
    __syncthreads();   // u1S/u2S/boS visible; qS/kS per-warp also done

    // scores: 64 per edge, lane handles s = l and s = l+32
    float a_out[2];
#pragma unroll
    for (int i = 0; i < 2; i++) {
        int s = l + 32 * i;
        int qp = s >> 4, hh = (s >> 2) & 3, kp = s & 3;
        const float* qp_ = &qS[w][qp * 64 + hh * 16];
        const float* kp_ = &kS[w][kp * 64 + hh * 16];
        float d = 0.f;
#pragma unroll
        for (int j = 0; j < 4; j++) {
            float4 qv = *reinterpret_cast<const float4*>(qp_ + 4 * j);
            float4 kv = *reinterpret_cast<const float4*>(kp_ + 4 * j);
            d = fmaf(qv.x, kv.x, d); d = fmaf(qv.y, kv.y, d);
            d = fmaf(qv.z, kv.z, d); d = fmaf(qv.w, kv.w, d);
        }
        float sc = d * 0.25f;   // SCALE = HD^-0.5
        // softmax over the quad (kp = lane&3 within each group of 4 lanes)
        float mx = sc;
        mx = fmaxf(mx, __shfl_xor_sync(0xffffffffu, mx, 1));
        mx = fmaxf(mx, __shfl_xor_sync(0xffffffffu, mx, 2));
        float ex = __expf(sc - mx);
        float ssum = ex;
        ssum += __shfl_xor_sync(0xffffffffu, ssum, 1);
        ssum += __shfl_xor_sync(0xffffffffu, ssum, 2);
        a_out[i] = ex / ssum;
    }
    aS[w][l] = a_out[0];
    aS[w][l + 32] = a_out[1];
    __syncwarp();

    // per-edge folded V*Wout weights for this lane's two columns c = 2l, 2l+1
    float2 wv[16];
#pragma unroll
    for (int kh = 0; kh < 16; kh++) {
        float2 u1 = *reinterpret_cast<const float2*>(&u1S[kh][2 * l]);
        float2 u2 = *reinterpret_cast<const float2*>(&u2S[kh][2 * l]);
        wv[kh].x = fmaf(eav, u1.x, u2.x);
        wv[kh].y = fmaf(eav, u1.y, u2.y);
    }
    float2 bo = *reinterpret_cast<const float2*>(&boS[2 * l]);

    float* dst = outAcc + (size_t)d_node * 256;
#pragma unroll
    for (int qp = 0; qp < 4; qp++) {
        const float4* ap = reinterpret_cast<const float4*>(&aS[w][qp * 16]);
        float mX = 0.f, mY = 0.f;
#pragma unroll
        for (int h = 0; h < 4; h++) {
            float4 av = ap[h];   // kp = 0..3 for this head
            mX = fmaf(av.x, wv[h * 4 + 0].x, mX);
            mX = fmaf(av.y, wv[h * 4 + 1].x, mX);
            mX = fmaf(av.z, wv[h * 4 + 2].x, mX);
            mX = fmaf(av.w, wv[h * 4 + 3].x, mX);
            mY = fmaf(av.x, wv[h * 4 + 0].y, mY);
            mY = fmaf(av.y, wv[h * 4 + 1].y, mY);
            mY = fmaf(av.z, wv[h * 4 + 2].y, mY);
            mY = fmaf(av.w, wv[h * 4 + 3].y, mY);
        }
        mX += bo.x;
        mY += bo.y;
        float* p = dst + qp * 64 + 2 * l;
        asm volatile("red.global.add.v2.f32 [%0], {%1, %2};"
                     :: "l"(p), "f"(mX), "f"(mY) : "memory");
    }
}

// ======================================================================
// launch
// ======================================================================
extern "C" void kernel_launch(void* const* d_in, const int* in_sizes, int n_in,
                              void* d_out, int out_size)
{
    const float* x_a   = (const float*)d_in[0];
    const float* x_b   = (const float*)d_in[1];
    const int*   ei1   = (const int*)  d_in[2];
    const float* ea1   = (const float*)d_in[3];
    const int*   ei2   = (const int*)  d_in[4];
    const float* ea2   = (const float*)d_in[5];
    const float* Wn_a  = (const float*)d_in[6];
    const float* bn_a  = (const float*)d_in[7];
    const float* Wn_b  = (const float*)d_in[8];
    const float* bn_b  = (const float*)d_in[9];
    const float* We1   = (const float*)d_in[10];
    const float* be1   = (const float*)d_in[11];
    const float* Win1  = (const float*)d_in[12];
    const float* bin1  = (const float*)d_in[13];
    const float* Wout1 = (const float*)d_in[14];
    const float* bout1 = (const float*)d_in[15];
    const float* We2   = (const float*)d_in[16];
    const float* be2   = (const float*)d_in[17];
    const float* Win2  = (const float*)d_in[18];
    const float* bin2  = (const float*)d_in[19];
    const float* Wout2 = (const float*)d_in[20];
    const float* bout2 = (const float*)d_in[21];
    const float* Wo_a  = (const float*)d_in[22];
    const float* bo_a  = (const float*)d_in[23];
    const float* Wo_b  = (const float*)d_in[24];
    const float* bo_b  = (const float*)d_in[25];
    const float* ln_g  = (const float*)d_in[26];
    const float* ln_b  = (const float*)d_in[27];
    float* y = (float*)d_out;

    float *xpa, *xpb, *oa, *ob, *q1, *k1, *q2, *k2, *u1p, *u2p;
    cudaGetSymbolAddress((void**)&xpa, g_xp_a);
    cudaGetSymbolAddress((void**)&xpb, g_xp_b);
    cudaGetSymbolAddress((void**)&oa,  g_out_a);
    cudaGetSymbolAddress((void**)&ob,  g_out_b);
    cudaGetSymbolAddress((void**)&q1,  g_Q1);
    cudaGetSymbolAddress((void**)&k1,  g_K1);
    cudaGetSymbolAddress((void**)&q2,  g_Q2);
    cudaGetSymbolAddress((void**)&k2,  g_K2);
    cudaGetSymbolAddress((void**)&u1p, g_U1);
    cudaGetSymbolAddress((void**)&u2p, g_U2);

    cudaFuncSetAttribute(qk_kernel, cudaFuncAttributeMaxDynamicSharedMemorySize,
                         (int)sizeof(QKSmem));

    // node projections
    gemm_bias_kernel<<<NNODES / 32, 256>>>(x_a, Wn_a, bn_a, xpa);
    gemm_bias_kernel<<<NNODES / 32, 256>>>(x_b, Wn_b, bn_b, xpb);

    // tiny folded tables (independent of xp; can run any time before edges)
    setup_kernel<<<1, 256>>>(We1, be1, Win1, bin1, Wout1, u1p, u2p);
    setup_kernel<<<1, 256>>>(We2, be2, Win2, bin2, Wout2, u1p + 1024, u2p + 1024);

    // Q/K tables: from xp_a -> Q2 (Wq2), K1 (Wk1); from xp_b -> Q1 (Wq1), K2 (Wk2)
    // Win layout: rows [0,64)=Wq, [64,128)=Wk, [128,192)=Wv ; bin likewise.
    qk_kernel<<<NNODES * 4 / 64, 256, sizeof(QKSmem)>>>(
        xpa, Win2, bin2, Win1 + 64 * 64, bin1 + 64, q2, k1);
    qk_kernel<<<NNODES * 4 / 64, 256, sizeof(QKSmem)>>>(
        xpb, Win1, bin1, Win2 + 64 * 64, bin2 + 64, q1, k2);

    // zero accumulators
    zero_kernel<<<2048, 256>>>((float4*)oa, (float4*)ob, NNODES * CDIM / 4);

    // edge messages: set1 -> out_b (dst = ei1[1] in xp_b), set2 -> out_a
    edge_kernel2<<<NEDGES / EPB, 256>>>(q1, k1, ei1, ea1, u1p, u2p, bout1, ob);
    edge_kernel2<<<NEDGES / EPB, 256>>>(q2, k2, ei2, ea2, u1p + 1024, u2p + 1024, bout2, oa);

    // output projection + layernorm
    gemm_ln_kernel<<<NNODES / 32, 256>>>(oa, Wo_a, bo_a, ln_g, ln_b, y);
    gemm_ln_kernel<<<NNODES / 32, 256>>>(ob, Wo_b, bo_b, ln_g, ln_b,
                                         y + (size_t)NNODES * CDIM);
}